// round 8
// baseline (speedup 1.0000x reference)
#include <cuda_runtime.h>
#include <math.h>
#include <stdint.h>

#define VOL (128*128*128)

// Accumulators (double): 0 reg_sumsq | 1-3 pair0 cross/gg/pp | 4-6 pair1 | 7-8 tv0 prod/sum | 9-10 tv1
// Zero at load; last-finishing block emits result and re-zeroes for next replay.
__device__ double g_acc[12];
__device__ unsigned g_ticket;

__device__ __forceinline__ float warp_sum(float v) {
    #pragma unroll
    for (int o = 16; o > 0; o >>= 1) v += __shfl_xor_sync(0xffffffffu, v, o);
    return v;
}

__device__ __forceinline__ void cp16(uint32_t dst, const float* src, int bytes) {
    asm volatile("cp.async.cg.shared.global [%0], [%1], 16, %2;"
                 :: "r"(dst), "l"(src), "r"(bytes));
}
#define CP_COMMIT() asm volatile("cp.async.commit_group;")
#define CP_WAIT0()  asm volatile("cp.async.wait_group 0;")

#define LCC_BLOCKS 256
#define REG_BLOCKS 512
#define TV_BLOCKS  256
#define TOTAL_BLOCKS (LCC_BLOCKS + REG_BLOCKS + TV_BLOCKS)

// LCC tile: x=128 (full volume width, no x-halo), y=8 outputs (12 with halo),
// z=32 march (36 slices). 256 threads: thread = (lx 0..31 -> 4 x's, ly 0..7 -> row).
#define NSLICE 36
#define BUF_FLOATS (2*12*128)   // floats per buffer (2 arrays x 12 rows x 128)

__global__ __launch_bounds__(256, 3) void fused_kernel(
    const float* __restrict__ F0, const float* __restrict__ F0g,
    const float* __restrict__ I0, const float* __restrict__ I0R,
    const float* __restrict__ I1, const float* __restrict__ I1R,
    const float* __restrict__ S0, const float* __restrict__ S0g,
    const float* __restrict__ S1, const float* __restrict__ S1g,
    float* __restrict__ out) {

    __shared__ float raw[2][2][12][128];   // [buf][arr][row][x]  24576 B
    __shared__ float xs[2][2][12][128];    // x-window sums       24576 B

    int blkid = blockIdx.x;
    int tid = threadIdx.x;

    if (blkid < LCC_BLOCKS) {
        // ================= LCC =================
        int blk = blkid;
        int y0 = (blk & 15) * 8;
        int z0 = ((blk >> 4) & 3) * 32;
        int batch = (blk >> 6) & 1;
        int pair = blk >> 7;

        const float* gt = (pair == 0 ? I0 : I1) + (size_t)batch * VOL;
        const float* pr = (pair == 0 ? I0R : I1R) + (size_t)batch * VOL;

        int lx = tid & 31, ly = tid >> 5;
        int zbase = z0 - 2;

        // ---- cp.async roles: 768 float4 per slice (2 arr x 12 rows x 32), 3 per thread
        const float* srcBaseK[3];
        int dstOffK[3];
        bool vyK[3];
        #pragma unroll
        for (int k = 0; k < 3; k++) {
            int r = tid + k * 256;
            int arr = r / 384;
            int q = r - arr * 384;
            int rr = q >> 5;
            int cc4 = (q & 31) * 4;
            int gy = y0 + rr - 2;
            bool vy = (unsigned)gy < 128u;
            srcBaseK[k] = (arr ? pr : gt) + (vy ? gy * 128 + cc4 : 0);
            dstOffK[k] = (arr * 12 + rr) * 128 + cc4;
            vyK[k] = vy;
        }
        uint32_t sraw = (uint32_t)__cvta_generic_to_shared(&raw[0][0][0][0]);

        // prologue: slice 0 -> buf 0
        {
            int zz = zbase;
            bool vz = (unsigned)zz < 128u;
            long zoff = vz ? (long)zz * 16384 : 0;
            #pragma unroll
            for (int k = 0; k < 3; k++)
                cp16(sraw + dstOffK[k] * 4, srcBaseK[k] + zoff, (vz && vyK[k]) ? 16 : 0);
            CP_COMMIT();
            CP_WAIT0();
        }
        __syncthreads();

        float4 bg[5], bp[5];
        #pragma unroll
        for (int k = 0; k < 5; k++) {
            bg[k] = make_float4(0.f, 0.f, 0.f, 0.f);
            bp[k] = make_float4(0.f, 0.f, 0.f, 0.f);
        }
        float accC = 0.f, accG = 0.f, accP = 0.f;

        // center pointers (output voxel is always in-volume)
        const float* ctrG = gt + (y0 + ly) * 128 + 4 * lx;
        const float* ctrP = pr + (y0 + ly) * 128 + 4 * lx;

        bool roleB = (tid < 128);   // rows 8..11 handled by warps 0..3

        #pragma unroll
        for (int zi = 0; zi < NSLICE; zi++) {
            const int cur = zi & 1, nxt = cur ^ 1;

            // prefetch slice zi+1 into raw[nxt] via cp.async
            if (zi + 1 < NSLICE) {
                int zz = zbase + zi + 1;
                bool vz = (unsigned)zz < 128u;
                long zoff = vz ? (long)zz * 16384 : 0;
                #pragma unroll
                for (int k = 0; k < 3; k++)
                    cp16(sraw + (nxt * BUF_FLOATS + dstOffK[k]) * 4,
                         srcBaseK[k] + zoff, (vz && vyK[k]) ? 16 : 0);
                CP_COMMIT();
            }

            // ---- x-pass: 5-wide window along x, float4 granularity
            #pragma unroll
            for (int arr = 0; arr < 2; arr++) {
                {
                    const float4* rp = (const float4*)&raw[cur][arr][ly][0];
                    float4 b = rp[lx];
                    float4 a = make_float4(0.f, 0.f, 0.f, 0.f), c = a;
                    if (lx > 0) a = rp[lx - 1];
                    if (lx < 31) c = rp[lx + 1];
                    float m = b.x + b.y + b.z;
                    float4 s;
                    s.x = a.z + a.w + m;
                    s.y = a.w + m + b.w;
                    s.z = m + b.w + c.x;
                    s.w = b.y + b.z + b.w + c.x + c.y;
                    *(float4*)&xs[cur][arr][ly][4 * lx] = s;
                }
                if (roleB) {
                    const float4* rp = (const float4*)&raw[cur][arr][8 + ly][0];
                    float4 b = rp[lx];
                    float4 a = make_float4(0.f, 0.f, 0.f, 0.f), c = a;
                    if (lx > 0) a = rp[lx - 1];
                    if (lx < 31) c = rp[lx + 1];
                    float m = b.x + b.y + b.z;
                    float4 s;
                    s.x = a.z + a.w + m;
                    s.y = a.w + m + b.w;
                    s.z = m + b.w + c.x;
                    s.w = b.y + b.z + b.w + c.x + c.y;
                    *(float4*)&xs[cur][arr][8 + ly][4 * lx] = s;
                }
            }

            if (zi + 1 < NSLICE) CP_WAIT0();
            __syncthreads();

            // ---- y-pass: 5-row window, z held in float4 register ring
            {
                float4 w0 = *(const float4*)&xs[cur][0][ly + 0][4 * lx];
                float4 w1 = *(const float4*)&xs[cur][0][ly + 1][4 * lx];
                float4 w2 = *(const float4*)&xs[cur][0][ly + 2][4 * lx];
                float4 w3 = *(const float4*)&xs[cur][0][ly + 3][4 * lx];
                float4 w4 = *(const float4*)&xs[cur][0][ly + 4][4 * lx];
                bg[zi % 5] = make_float4(w0.x + w1.x + w2.x + w3.x + w4.x,
                                         w0.y + w1.y + w2.y + w3.y + w4.y,
                                         w0.z + w1.z + w2.z + w3.z + w4.z,
                                         w0.w + w1.w + w2.w + w3.w + w4.w);
                float4 u0 = *(const float4*)&xs[cur][1][ly + 0][4 * lx];
                float4 u1 = *(const float4*)&xs[cur][1][ly + 1][4 * lx];
                float4 u2 = *(const float4*)&xs[cur][1][ly + 2][4 * lx];
                float4 u3 = *(const float4*)&xs[cur][1][ly + 3][4 * lx];
                float4 u4 = *(const float4*)&xs[cur][1][ly + 4][4 * lx];
                bp[zi % 5] = make_float4(u0.x + u1.x + u2.x + u3.x + u4.x,
                                         u0.y + u1.y + u2.y + u3.y + u4.y,
                                         u0.z + u1.z + u2.z + u3.z + u4.z,
                                         u0.w + u1.w + u2.w + u3.w + u4.w);
            }

            if (zi >= 4) {
                float4 SG = make_float4(bg[0].x + bg[1].x + bg[2].x + bg[3].x + bg[4].x,
                                        bg[0].y + bg[1].y + bg[2].y + bg[3].y + bg[4].y,
                                        bg[0].z + bg[1].z + bg[2].z + bg[3].z + bg[4].z,
                                        bg[0].w + bg[1].w + bg[2].w + bg[3].w + bg[4].w);
                float4 SP = make_float4(bp[0].x + bp[1].x + bp[2].x + bp[3].x + bp[4].x,
                                        bp[0].y + bp[1].y + bp[2].y + bp[3].y + bp[4].y,
                                        bp[0].z + bp[1].z + bp[2].z + bp[3].z + bp[4].z,
                                        bp[0].w + bp[1].w + bp[2].w + bp[3].w + bp[4].w);
                long zo = (long)(zbase + zi - 2) * 16384;
                float4 CG = __ldg((const float4*)(ctrG + zo));
                float4 CP = __ldg((const float4*)(ctrP + zo));
                const float kinv = 1.f / 125.f;
                float g0v = CG.x - SG.x * kinv, g1v = CG.y - SG.y * kinv;
                float g2v = CG.z - SG.z * kinv, g3v = CG.w - SG.w * kinv;
                float p0v = CP.x - SP.x * kinv, p1v = CP.y - SP.y * kinv;
                float p2v = CP.z - SP.z * kinv, p3v = CP.w - SP.w * kinv;
                accG += g0v * g0v + g1v * g1v + g2v * g2v + g3v * g3v;
                accP += p0v * p0v + p1v * p1v + p2v * p2v + p3v * p3v;
                accC += g0v * p0v + g1v * p1v + g2v * p2v + g3v * p3v;
            }
        }

        float* scr = &raw[0][0][0][0];
        float c = warp_sum(accC);
        float gg = warp_sum(accG);
        float pp = warp_sum(accP);
        int wid = tid >> 5, lane = tid & 31;
        __syncthreads();
        if (lane == 0) { scr[wid] = c; scr[8 + wid] = gg; scr[16 + wid] = pp; }
        __syncthreads();
        if (tid == 0) {
            float C = 0, G = 0, P = 0;
            #pragma unroll
            for (int w = 0; w < 8; w++) { C += scr[w]; G += scr[8 + w]; P += scr[16 + w]; }
            int base = 1 + pair * 3;
            atomicAdd(&g_acc[base + 0], (double)C);
            atomicAdd(&g_acc[base + 1], (double)G);
            atomicAdd(&g_acc[base + 2], (double)P);
        }
    } else if (blkid < LCC_BLOCKS + REG_BLOCKS) {
        // ================= reg_field: sum((a-b)^2) =================
        const float4* a = (const float4*)F0;
        const float4* b = (const float4*)F0g;
        const int n4 = (2 * 3 * VOL) / 4;
        int bid = blkid - LCC_BLOCKS;
        float acc = 0.f;
        for (int i = bid * 256 + tid; i < n4; i += REG_BLOCKS * 256) {
            float4 x = a[i], y = b[i];
            float d0 = x.x - y.x, d1 = x.y - y.y, d2 = x.z - y.z, d3 = x.w - y.w;
            acc += d0 * d0 + d1 * d1 + d2 * d2 + d3 * d3;
        }
        float* scr = &raw[0][0][0][0];
        float w = warp_sum(acc);
        if ((tid & 31) == 0) scr[tid >> 5] = w;
        __syncthreads();
        if (tid == 0) {
            float v = 0.f;
            #pragma unroll
            for (int k = 0; k < 8; k++) v += scr[k];
            atomicAdd(&g_acc[0], (double)v);
        }
    } else {
        // ================= tversky: both pairs =================
        const float4* g0 = (const float4*)S0;
        const float4* p0 = (const float4*)S0g;
        const float4* g1 = (const float4*)S1;
        const float4* p1 = (const float4*)S1g;
        const int n4 = (2 * VOL) / 4;
        int bid = blkid - LCC_BLOCKS - REG_BLOCKS;
        float pr0 = 0.f, sm0 = 0.f, pr1 = 0.f, sm1 = 0.f;
        for (int i = bid * 256 + tid; i < n4; i += TV_BLOCKS * 256) {
            float4 a = g0[i], b = p0[i];
            pr0 += a.x * b.x + a.y * b.y + a.z * b.z + a.w * b.w;
            sm0 += a.x + b.x + a.y + b.y + a.z + b.z + a.w + b.w;
            float4 cc = g1[i], dd = p1[i];
            pr1 += cc.x * dd.x + cc.y * dd.y + cc.z * dd.z + cc.w * dd.w;
            sm1 += cc.x + dd.x + cc.y + dd.y + cc.z + dd.z + cc.w + dd.w;
        }
        float* scr = &raw[0][0][0][0];
        float v0 = warp_sum(pr0), v1 = warp_sum(sm0), v2 = warp_sum(pr1), v3 = warp_sum(sm1);
        int wid = tid >> 5;
        if ((tid & 31) == 0) { scr[wid] = v0; scr[8 + wid] = v1; scr[16 + wid] = v2; scr[24 + wid] = v3; }
        __syncthreads();
        if (tid == 0) {
            float t0 = 0, t1 = 0, t2 = 0, t3 = 0;
            #pragma unroll
            for (int k = 0; k < 8; k++) { t0 += scr[k]; t1 += scr[8 + k]; t2 += scr[16 + k]; t3 += scr[24 + k]; }
            atomicAdd(&g_acc[7], (double)t0);
            atomicAdd(&g_acc[8], (double)t1);
            atomicAdd(&g_acc[9], (double)t2);
            atomicAdd(&g_acc[10], (double)t3);
        }
    }

    // ---- last-block-done finalize ----
    if (tid == 0) {
        __threadfence();
        unsigned t = atomicAdd(&g_ticket, 1u);
        if (t == TOTAL_BLOCKS - 1) {
            __threadfence();
            volatile double* acc = g_acc;

            const double omega_f = 2.0 * 3.0 * VOL;
            const double omega_i = 2.0 * 1.0 * VOL;

            double rf = sqrt(acc[0]) / omega_f;

            double num0 = acc[1] * acc[1];
            double den0 = acc[2] * acc[3];
            den0 = den0 > 1e-5 ? den0 : 1e-5;
            double lcc0 = -(num0 / den0) / omega_i;

            double num1 = acc[4] * acc[4];
            double den1 = acc[5] * acc[6];
            den1 = den1 > 1e-5 ? den1 : 1e-5;
            double lcc1 = -(num1 / den1) / omega_i;

            double s0 = acc[8] > 1e-5 ? acc[8] : 1e-5;
            double s1 = acc[10] > 1e-5 ? acc[10] : 1e-5;
            double tv0 = -acc[7] / s0;
            double tv1 = -acc[9] / s1;

            out[0] = (float)(rf + 10.0 * (lcc0 + lcc1) + 10.0 * (tv0 + tv1));

            #pragma unroll
            for (int k = 0; k < 12; k++) g_acc[k] = 0.0;
            __threadfence();
            g_ticket = 0u;
        }
    }
}

extern "C" void kernel_launch(void* const* d_in, const int* in_sizes, int n_in,
                              void* d_out, int out_size) {
    const float* F0  = (const float*)d_in[0];
    const float* F0g = (const float*)d_in[1];
    const float* I0  = (const float*)d_in[2];
    const float* I0R = (const float*)d_in[3];
    const float* I1  = (const float*)d_in[4];
    const float* I1R = (const float*)d_in[5];
    const float* S0  = (const float*)d_in[6];
    const float* S0g = (const float*)d_in[7];
    const float* S1  = (const float*)d_in[8];
    const float* S1g = (const float*)d_in[9];
    float* out = (float*)d_out;

    fused_kernel<<<TOTAL_BLOCKS, 256>>>(F0, F0g, I0, I0R, I1, I1R,
                                        S0, S0g, S1, S1g, out);
}

// round 9
// speedup vs baseline: 1.0676x; 1.0676x over previous
#include <cuda_runtime.h>
#include <math.h>

#define VOL (128*128*128)

// Accumulators (double): 0 reg_sumsq | 1-3 pair0 cross/gg/pp | 4-6 pair1 | 7-8 tv0 prod/sum | 9-10 tv1
// Zero at load; last-finishing block emits result and re-zeroes for next replay.
__device__ double g_acc[12];
__device__ unsigned g_ticket;

__device__ __forceinline__ float warp_sum(float v) {
    #pragma unroll
    for (int o = 16; o > 0; o >>= 1) v += __shfl_xor_sync(0xffffffffu, v, o);
    return v;
}

// ---------------------------------------------------------------------------
// LCC geometry: tile 64(x) x 8(y) x 32(z), halo 2. gt/pred packed in SMEM as
// float4 {g0,g1,p0,p1} per x-float2 so every shared op serves both arrays.
// One barrier per z-slice; z-window in a float4 register ring.
// ---------------------------------------------------------------------------
#define TY 8
#define TZ 32
#define HX4 34            // raw row width in packed float4 (x-float2 cols)
#define HY 12
#define NSLICE (TZ + 4)   // 36
#define RAW_E (HY * HX4)  // 408 packed elements per slice

#define LCC_BLOCKS 512
#define REG_BLOCKS 512
#define TV_BLOCKS  256
#define TOTAL_BLOCKS (LCC_BLOCKS + REG_BLOCKS + TV_BLOCKS)

__global__ __launch_bounds__(256, 4) void fused_kernel(
    const float* __restrict__ F0, const float* __restrict__ F0g,
    const float* __restrict__ I0, const float* __restrict__ I0R,
    const float* __restrict__ I1, const float* __restrict__ I1R,
    const float* __restrict__ S0, const float* __restrict__ S0g,
    const float* __restrict__ S1, const float* __restrict__ S1g,
    float* __restrict__ out) {

    __shared__ float4 raw[2][HY][HX4];   // {g0,g1,p0,p1}  13056 B
    __shared__ float4 xs[2][HY][32];     // x-window sums  12288 B

    int blkid = blockIdx.x;
    int tid = threadIdx.x;

    if (blkid < LCC_BLOCKS) {
        // ================= LCC =================
        int blk = blkid;
        int x2_0 = (blk & 1) * 32;            // tile x origin in float2 units
        int y0 = ((blk >> 1) & 15) * TY;
        int z0 = ((blk >> 5) & 3) * TZ;
        int batch = (blk >> 7) & 1;
        int pair = blk >> 8;

        const float2* gt = (const float2*)((pair == 0 ? I0 : I1) + (size_t)batch * VOL);
        const float2* pr = (const float2*)((pair == 0 ? I0R : I1R) + (size_t)batch * VOL);

        int lx = tid & 31, ly = tid >> 5;

        // ---- load roles (packed elements, 408 per slice)
        int e0 = tid, e1 = tid + 256;
        int r0 = e0 / HX4, c0 = e0 - r0 * HX4;
        int r1 = e1 / HX4, c1 = e1 - r1 * HX4;
        int gxa = x2_0 - 1 + c0, gya = y0 + r0 - 2;
        int gxb = x2_0 - 1 + c1, gyb = y0 + r1 - 2;
        bool hasE1 = (e1 < RAW_E);            // tid < 152
        bool va = ((unsigned)gxa < 64u) & ((unsigned)gya < 128u);
        bool vb = hasE1 & ((unsigned)gxb < 64u) & ((unsigned)gyb < 128u);
        int zbase = z0 - 2;
        long zb = (long)zbase * 8192;         // slice stride in float2
        const float2* pga = gt + (va ? (gya * 64 + gxa) : 0) + zb;
        const float2* ppa = pr + (va ? (gya * 64 + gxa) : 0) + zb;
        const float2* pgb = gt + (vb ? (gyb * 64 + gxb) : 0) + zb;
        const float2* ppb = pr + (vb ? (gyb * 64 + gxb) : 0) + zb;

        // prologue: slice 0 into buffer 0
        {
            bool zv = (unsigned)zbase < 128u;
            float2 ga = make_float2(0.f, 0.f), pa = ga, gb = ga, pb = ga;
            if (va & zv) { ga = pga[0]; pa = ppa[0]; }
            if (vb & zv) { gb = pgb[0]; pb = ppb[0]; }
            raw[0][r0][c0] = make_float4(ga.x, ga.y, pa.x, pa.y);
            if (hasE1) raw[0][r1][c1] = make_float4(gb.x, gb.y, pb.x, pb.y);
        }
        __syncthreads();

        float4 ring[5], c3[3];
        #pragma unroll
        for (int k = 0; k < 5; k++) ring[k] = make_float4(0.f, 0.f, 0.f, 0.f);
        #pragma unroll
        for (int k = 0; k < 3; k++) c3[k] = make_float4(0.f, 0.f, 0.f, 0.f);
        float accC = 0.f, accG = 0.f, accP = 0.f;

        #pragma unroll
        for (int zi = 0; zi < NSLICE; zi++) {
            const int cur = zi & 1, nxt = cur ^ 1;

            // prefetch slice zi+1 (overlaps x-pass)
            float2 nga = make_float2(0.f, 0.f), npa = nga, ngb = nga, npb = nga;
            if (zi + 1 < NSLICE) {
                bool zv = (unsigned)(zbase + zi + 1) < 128u;
                const int zo = (zi + 1) * 8192;
                if (va & zv) { nga = pga[zo]; npa = ppa[zo]; }
                if (vb & zv) { ngb = pgb[zo]; npb = ppb[zo]; }
            }

            // ---- x-pass: window cols lx, lx+1, lx+2 -> sums for outputs 2lx, 2lx+1
            {
                const float4* rp = &raw[cur][ly][0];
                float4 a = rp[lx], b = rp[lx + 1], c = rp[lx + 2];
                float tg = a.y + b.x + b.y + c.x;
                float tp = a.w + b.z + b.w + c.z;
                xs[cur][ly][lx] = make_float4(a.x + tg, tg + c.y, a.z + tp, tp + c.w);
                if (tid < 128) {
                    const float4* rp2 = &raw[cur][8 + ly][0];
                    float4 a2 = rp2[lx], b2 = rp2[lx + 1], c2 = rp2[lx + 2];
                    float tg2 = a2.y + b2.x + b2.y + c2.x;
                    float tp2 = a2.w + b2.z + b2.w + c2.z;
                    xs[cur][8 + ly][lx] = make_float4(a2.x + tg2, tg2 + c2.y, a2.z + tp2, tp2 + c2.w);
                }
                // centers for outputs (2lx, 2lx+1): packed col lx+1, row ly+2
                c3[zi % 3] = raw[cur][ly + 2][lx + 1];
            }

            // stage prefetched slice into raw[nxt]
            raw[nxt][r0][c0] = make_float4(nga.x, nga.y, npa.x, npa.y);
            if (hasE1) raw[nxt][r1][c1] = make_float4(ngb.x, ngb.y, npb.x, npb.y);
            __syncthreads();

            // ---- y-pass: 5-row window; z held in float4 register ring
            {
                float4 w0 = xs[cur][ly + 0][lx];
                float4 w1 = xs[cur][ly + 1][lx];
                float4 w2 = xs[cur][ly + 2][lx];
                float4 w3 = xs[cur][ly + 3][lx];
                float4 w4 = xs[cur][ly + 4][lx];
                ring[zi % 5] = make_float4(w0.x + w1.x + w2.x + w3.x + w4.x,
                                           w0.y + w1.y + w2.y + w3.y + w4.y,
                                           w0.z + w1.z + w2.z + w3.z + w4.z,
                                           w0.w + w1.w + w2.w + w3.w + w4.w);
            }

            if (zi >= 4) {
                float4 S = make_float4(ring[0].x + ring[1].x + ring[2].x + ring[3].x + ring[4].x,
                                       ring[0].y + ring[1].y + ring[2].y + ring[3].y + ring[4].y,
                                       ring[0].z + ring[1].z + ring[2].z + ring[3].z + ring[4].z,
                                       ring[0].w + ring[1].w + ring[2].w + ring[3].w + ring[4].w);
                float4 C = c3[(zi - 2) % 3];
                const float kinv = 1.f / 125.f;
                float dg0 = C.x - S.x * kinv;
                float dg1 = C.y - S.y * kinv;
                float dp0 = C.z - S.z * kinv;
                float dp1 = C.w - S.w * kinv;
                accG += dg0 * dg0 + dg1 * dg1;
                accP += dp0 * dp0 + dp1 * dp1;
                accC += dg0 * dp0 + dg1 * dp1;
            }
        }

        float* scr = (float*)&xs[0][0][0];
        float c = warp_sum(accC);
        float gg = warp_sum(accG);
        float pp = warp_sum(accP);
        int wid = tid >> 5, lane = tid & 31;
        __syncthreads();
        if (lane == 0) { scr[wid] = c; scr[8 + wid] = gg; scr[16 + wid] = pp; }
        __syncthreads();
        if (tid == 0) {
            float C = 0, G = 0, P = 0;
            #pragma unroll
            for (int w = 0; w < 8; w++) { C += scr[w]; G += scr[8 + w]; P += scr[16 + w]; }
            int base = 1 + pair * 3;
            atomicAdd(&g_acc[base + 0], (double)C);
            atomicAdd(&g_acc[base + 1], (double)G);
            atomicAdd(&g_acc[base + 2], (double)P);
        }
    } else if (blkid < LCC_BLOCKS + REG_BLOCKS) {
        // ================= reg_field: sum((a-b)^2) =================
        const float4* a = (const float4*)F0;
        const float4* b = (const float4*)F0g;
        const int n4 = (2 * 3 * VOL) / 4;
        int bid = blkid - LCC_BLOCKS;
        float acc = 0.f;
        for (int i = bid * 256 + tid; i < n4; i += REG_BLOCKS * 256) {
            float4 x = a[i], y = b[i];
            float d0 = x.x - y.x, d1 = x.y - y.y, d2 = x.z - y.z, d3 = x.w - y.w;
            acc += d0 * d0 + d1 * d1 + d2 * d2 + d3 * d3;
        }
        float* scr = (float*)&xs[0][0][0];
        float w = warp_sum(acc);
        if ((tid & 31) == 0) scr[tid >> 5] = w;
        __syncthreads();
        if (tid == 0) {
            float v = 0.f;
            #pragma unroll
            for (int k = 0; k < 8; k++) v += scr[k];
            atomicAdd(&g_acc[0], (double)v);
        }
    } else {
        // ================= tversky: both pairs =================
        const float4* g0 = (const float4*)S0;
        const float4* p0 = (const float4*)S0g;
        const float4* g1 = (const float4*)S1;
        const float4* p1 = (const float4*)S1g;
        const int n4 = (2 * VOL) / 4;
        int bid = blkid - LCC_BLOCKS - REG_BLOCKS;
        float pr0 = 0.f, sm0 = 0.f, pr1 = 0.f, sm1 = 0.f;
        for (int i = bid * 256 + tid; i < n4; i += TV_BLOCKS * 256) {
            float4 a = g0[i], b = p0[i];
            pr0 += a.x * b.x + a.y * b.y + a.z * b.z + a.w * b.w;
            sm0 += a.x + b.x + a.y + b.y + a.z + b.z + a.w + b.w;
            float4 cc = g1[i], dd = p1[i];
            pr1 += cc.x * dd.x + cc.y * dd.y + cc.z * dd.z + cc.w * dd.w;
            sm1 += cc.x + dd.x + cc.y + dd.y + cc.z + dd.z + cc.w + dd.w;
        }
        float* scr = (float*)&xs[0][0][0];
        float v0 = warp_sum(pr0), v1 = warp_sum(sm0), v2 = warp_sum(pr1), v3 = warp_sum(sm1);
        int wid = tid >> 5;
        if ((tid & 31) == 0) { scr[wid] = v0; scr[8 + wid] = v1; scr[16 + wid] = v2; scr[24 + wid] = v3; }
        __syncthreads();
        if (tid == 0) {
            float t0 = 0, t1 = 0, t2 = 0, t3 = 0;
            #pragma unroll
            for (int k = 0; k < 8; k++) { t0 += scr[k]; t1 += scr[8 + k]; t2 += scr[16 + k]; t3 += scr[24 + k]; }
            atomicAdd(&g_acc[7], (double)t0);
            atomicAdd(&g_acc[8], (double)t1);
            atomicAdd(&g_acc[9], (double)t2);
            atomicAdd(&g_acc[10], (double)t3);
        }
    }

    // ---- last-block-done finalize ----
    if (tid == 0) {
        __threadfence();
        unsigned t = atomicAdd(&g_ticket, 1u);
        if (t == TOTAL_BLOCKS - 1) {
            __threadfence();
            volatile double* acc = g_acc;

            const double omega_f = 2.0 * 3.0 * VOL;
            const double omega_i = 2.0 * 1.0 * VOL;

            double rf = sqrt(acc[0]) / omega_f;

            double num0 = acc[1] * acc[1];
            double den0 = acc[2] * acc[3];
            den0 = den0 > 1e-5 ? den0 : 1e-5;
            double lcc0 = -(num0 / den0) / omega_i;

            double num1 = acc[4] * acc[4];
            double den1 = acc[5] * acc[6];
            den1 = den1 > 1e-5 ? den1 : 1e-5;
            double lcc1 = -(num1 / den1) / omega_i;

            double s0 = acc[8] > 1e-5 ? acc[8] : 1e-5;
            double s1 = acc[10] > 1e-5 ? acc[10] : 1e-5;
            double tv0 = -acc[7] / s0;
            double tv1 = -acc[9] / s1;

            out[0] = (float)(rf + 10.0 * (lcc0 + lcc1) + 10.0 * (tv0 + tv1));

            #pragma unroll
            for (int k = 0; k < 12; k++) g_acc[k] = 0.0;
            __threadfence();
            g_ticket = 0u;
        }
    }
}

extern "C" void kernel_launch(void* const* d_in, const int* in_sizes, int n_in,
                              void* d_out, int out_size) {
    const float* F0  = (const float*)d_in[0];
    const float* F0g = (const float*)d_in[1];
    const float* I0  = (const float*)d_in[2];
    const float* I0R = (const float*)d_in[3];
    const float* I1  = (const float*)d_in[4];
    const float* I1R = (const float*)d_in[5];
    const float* S0  = (const float*)d_in[6];
    const float* S0g = (const float*)d_in[7];
    const float* S1  = (const float*)d_in[8];
    const float* S1g = (const float*)d_in[9];
    float* out = (float*)d_out;

    fused_kernel<<<TOTAL_BLOCKS, 256>>>(F0, F0g, I0, I0R, I1, I1R,
                                        S0, S0g, S1, S1g, out);
}